// round 12
// baseline (speedup 1.0000x reference)
#include <cuda_runtime.h>
#include <cuda_fp16.h>
#include <cstdint>

#define NN 100000
#define EE 1600000
#define DD 64
#define GRID_E 6250

// ---------------- scratch (device globals; no runtime allocation) ----------------
__device__ __align__(256) __half g_h16a [NN * DD];
__device__ __align__(256) __half g_h16b [NN * DD];
__device__ __align__(256) __half g_agg16[NN * DD];
__device__ __align__(256) __half g_w16[6 * 4096];   // Ws1,Wn1,Ws2,Wn2,Ws3,Wn3 fp16
__device__ int   g_cnt2[NN];     // atomic histogram (self-cleaning; starts zero)
__device__ int   g_cnt[NN];      // plain per-node degree
__device__ int   g_rowptr[NN];
__device__ int   g_cursor[NN];
__device__ int   g_col[EE];
__device__ float g_deginv[NN];
__device__ float g_t4[NN];
__device__ float g_u4[NN];
__device__ int   g_alloc;        // segment allocator (self-cleaning)
__device__ int   g_done;         // block done-counter (self-cleaning)

// ---------------- helpers ----------------
__device__ __forceinline__ uint32_t smem_u32(const void* p) {
    uint32_t a;
    asm("{ .reg .u64 t; cvta.to.shared.u64 t, %1; cvt.u32.u64 %0, t; }" : "=r"(a) : "l"(p));
    return a;
}
__device__ __forceinline__ long long edge_at(const void* ei, long long idx, int is64) {
    if (is64) return ((const long long*)ei)[idx];
    return (long long)((const int*)ei)[idx];
}
// per-warp dtype detection: high words of first 32 int64 pairs all zero => int64
__device__ __forceinline__ int detect64(const void* ei) {
    const unsigned* w = (const unsigned*)ei;
    unsigned lane = threadIdx.x & 31;
    bool z = (w[2 * lane + 1] == 0u);
    return __all_sync(0xffffffffu, z) ? 1 : 0;
}
__device__ __forceinline__ void ldsm_x4(uint32_t& r0, uint32_t& r1, uint32_t& r2,
                                        uint32_t& r3, uint32_t addr) {
    asm volatile("ldmatrix.sync.aligned.m8n8.x4.shared.b16 {%0,%1,%2,%3}, [%4];"
                 : "=r"(r0), "=r"(r1), "=r"(r2), "=r"(r3) : "r"(addr));
}
__device__ __forceinline__ void ldsm_x4_t(uint32_t& r0, uint32_t& r1, uint32_t& r2,
                                          uint32_t& r3, uint32_t addr) {
    asm volatile("ldmatrix.sync.aligned.m8n8.x4.trans.shared.b16 {%0,%1,%2,%3}, [%4];"
                 : "=r"(r0), "=r"(r1), "=r"(r2), "=r"(r3) : "r"(addr));
}
__device__ __forceinline__ void mma16816(float* d, uint32_t a0, uint32_t a1, uint32_t a2,
                                         uint32_t a3, uint32_t b0, uint32_t b1) {
    asm volatile(
        "mma.sync.aligned.m16n8k16.row.col.f32.f16.f16.f32 "
        "{%0,%1,%2,%3}, {%4,%5,%6,%7}, {%8,%9}, {%0,%1,%2,%3};"
        : "+f"(d[0]), "+f"(d[1]), "+f"(d[2]), "+f"(d[3])
        : "r"(a0), "r"(a1), "r"(a2), "r"(a3), "r"(b0), "r"(b1));
}
__device__ __forceinline__ int warp_iscan(int v, int lane) {
#pragma unroll
    for (int off = 1; off < 32; off <<= 1) {
        int t = __shfl_up_sync(0xffffffffu, v, off);
        if (lane >= off) v += t;
    }
    return v;
}

// ---------------- hist + x conv + weight conv (6250 edge blocks + 24 weight blocks) --
__global__ void k_hist(const void* __restrict__ ei, const float* __restrict__ x,
                       __half* __restrict__ o,
                       const float* __restrict__ Ws1, const float* __restrict__ Wn1,
                       const float* __restrict__ Ws2, const float* __restrict__ Wn2,
                       const float* __restrict__ Ws3, const float* __restrict__ Wn3) {
    if (blockIdx.x >= GRID_E) {
        int mb = blockIdx.x - GRID_E;       // 0..23
        int m = mb >> 2, seg = mb & 3;
        const float* srcs[6] = {Ws1, Wn1, Ws2, Wn2, Ws3, Wn3};
        const float* s = srcs[m];
        int base = seg * 1024;
        for (int i = threadIdx.x; i < 1024; i += 256)
            g_w16[m * 4096 + base + i] = __float2half_rn(s[base + i]);
        return;
    }
    int is64 = detect64(ei);
    int e = blockIdx.x * 256 + threadIdx.x;
    int d = (int)edge_at(ei, (long long)EE + e, is64);
    atomicAdd(&g_cnt2[d], 1);
    float4 v = ((const float4*)x)[e];
    ((__half2*)o)[2 * e]     = __floats2half2_rn(v.x, v.y);
    ((__half2*)o)[2 * e + 1] = __floats2half2_rn(v.z, v.w);
}

// ---------------- segment allocation (disjoint segments; one atomicAdd per warp) ----
__global__ void k_alloc() {
    int i = blockIdx.x * 256 + threadIdx.x;
    int lane = threadIdx.x & 31;
    int v = 0;
    if (i < NN) {
        v = g_cnt2[i];
        g_cnt2[i] = 0;                      // self-clean for next replay
        g_cnt[i] = v;
        g_deginv[i] = 1.0f / (float)(v > 0 ? v : 1);
    }
    int s = warp_iscan(v, lane);
    int wtot = __shfl_sync(0xffffffffu, s, 31);
    int base = 0;
    if (lane == 31) base = atomicAdd(&g_alloc, wtot);
    base = __shfl_sync(0xffffffffu, base, 31);
    if (i < NN) {
        int start = base + s - v;
        g_rowptr[i] = start;
        g_cursor[i] = start;
    }
    __syncthreads();
    if (threadIdx.x == 0) {
        int d = atomicAdd(&g_done, 1);
        if (d == (int)gridDim.x - 1) { g_alloc = 0; g_done = 0; }
    }
}

__global__ void k_fill(const void* __restrict__ ei) {
    int is64 = detect64(ei);
    int e = blockIdx.x * 256 + threadIdx.x;
    int dn = (int)edge_at(ei, (long long)EE + e, is64);
    int sn = (int)edge_at(ei, (long long)e, is64);
    int pos = atomicAdd(&g_cursor[dn], 1);
    g_col[pos] = sn;
}

// ---------------- aggregation: R10 pairwise body, 2 warps per node ----------------
// block = 256 thr = 8 warps = 4 nodes x 2 warps. Warp half h takes neighbor blocks
// j = 2g + 8h, stride 16. Same lean loop body as R10; combine halves via smem.
__global__ __launch_bounds__(256) void k_agg16(const __half* __restrict__ h,
                                               __half* __restrict__ a) {
    __shared__ float sred[4][64];
    int wid = threadIdx.x >> 5;
    int node = blockIdx.x * 4 + (wid >> 1);
    int half = wid & 1;
    int np = wid >> 1;                 // node slot in block (0..3)
    int lane = threadIdx.x & 31;
    int g  = lane >> 3;
    int fl = lane & 7;
    bool valid = (node < NN);

    int start = 0, cnt = 0;
    if (valid) { start = g_rowptr[node]; cnt = g_cnt[node]; }
    const int* __restrict__ col = g_col + start;

    float acc[8];
#pragma unroll
    for (int q = 0; q < 8; q++) acc[q] = 0.f;

    for (int j = 2 * g + 8 * half; j < cnt; j += 16) {
        int c0 = col[j];
        uint4 v0 = *(const uint4*)(h + (size_t)c0 * DD + fl * 8);
        uint4 v1 = make_uint4(0u, 0u, 0u, 0u);
        if (j + 1 < cnt) {
            int c1 = col[j + 1];
            v1 = *(const uint4*)(h + (size_t)c1 * DD + fl * 8);
        }
        const __half2* a0 = (const __half2*)&v0;
        const __half2* a1 = (const __half2*)&v1;
#pragma unroll
        for (int q = 0; q < 4; q++) {
            float2 f = __half22float2(__hadd2(a0[q], a1[q]));
            acc[2 * q]     += f.x;
            acc[2 * q + 1] += f.y;
        }
    }
#pragma unroll
    for (int q = 0; q < 8; q++) {
        acc[q] += __shfl_xor_sync(0xffffffffu, acc[q], 8);
        acc[q] += __shfl_xor_sync(0xffffffffu, acc[q], 16);
    }
    // half-1 warp publishes its partial; half-0 warp combines, scales, stores
    if (half == 1 && g == 0) {
#pragma unroll
        for (int q = 0; q < 8; q++) sred[np][fl * 8 + q] = acc[q];
    }
    __syncthreads();
    if (half == 0 && g == 0 && valid) {
        float di = g_deginv[node];
        __half2 o[4];
#pragma unroll
        for (int q = 0; q < 4; q++) {
            float x0 = (acc[2 * q]     + sred[np][fl * 8 + 2 * q])     * di;
            float x1 = (acc[2 * q + 1] + sred[np][fl * 8 + 2 * q + 1]) * di;
            o[q] = __floats2half2_rn(x0, x1);
        }
        *(uint4*)(a + (size_t)node * DD + fl * 8) = *(uint4*)o;
    }
}

// ---------------- HMMA fused GEMM + optional fused layer-4 linear ----------------
#define XS 136
#define WS2 72
#define OFF_WS (128 * XS)                      // halves
#define OFF_WN (OFF_WS + 64 * WS2)
#define OFF_BIAS_B ((OFF_WN + 64 * WS2) * 2)   // bytes
#define OFF_W4_B (OFF_BIAS_B + 64 * 4)
#define SMEM_HM (OFF_W4_B + 128 * 4)

__global__ __launch_bounds__(256) void k_gemm_hmma(
    const __half* __restrict__ h16, const __half* __restrict__ a16,
    int lidx, const float* __restrict__ bias, __half* __restrict__ out16,
    const float* __restrict__ ws4, const float* __restrict__ wn4,
    const float* __restrict__ b4, int do_lin4) {
    extern __shared__ char smem[];
    __half* sx = (__half*)smem;
    float* sbias = (float*)(smem + OFF_BIAS_B);
    float* sw4 = (float*)(smem + OFF_W4_B);
    uint32_t sb = smem_u32(smem);

    int tid = threadIdx.x, wid = tid >> 5, lane = tid & 31;
    int base = blockIdx.x * 128;

    const __half* w16 = g_w16 + lidx * 8192;   // Ws then Wn
    for (int idx = tid; idx < 1024; idx += 256) {
        int m = idx >> 9;
        int r = idx & 511;
        int k = r >> 3, ch = r & 7;
        uint4 v = ((const uint4*)(w16 + m * 4096))[r];
        *(uint4*)&sx[(m ? OFF_WN : OFF_WS) + k * WS2 + ch * 8] = v;
    }
    if (tid < 64) sbias[tid] = bias[tid];
    if (do_lin4 && tid < 64) { sw4[tid] = ws4[tid]; sw4[64 + tid] = wn4[tid]; }

    for (int idx = tid; idx < 128 * 16; idx += 256) {
        int r = idx >> 4, q = idx & 15;
        int node = base + r;
        uint4 v = make_uint4(0u, 0u, 0u, 0u);
        if (node < NN) {
            const __half* src = (q < 8) ? (h16 + (size_t)node * DD + q * 8)
                                        : (a16 + (size_t)node * DD + (q - 8) * 8);
            v = *(const uint4*)src;
        }
        *(uint4*)((char*)smem + (size_t)r * (XS * 2) + q * 16) = v;
    }
    __syncthreads();

    float acc[8][4];
#pragma unroll
    for (int nt = 0; nt < 8; nt++)
#pragma unroll
        for (int q = 0; q < 4; q++) acc[nt][q] = 0.f;

    int arow = wid * 16 + (lane & 15);
    int acolq = (lane >> 4) << 3;

#pragma unroll
    for (int ks = 0; ks < 8; ks++) {
        uint32_t a0, a1, a2, a3;
        ldsm_x4(a0, a1, a2, a3, sb + (arow * XS + ks * 16 + acolq) * 2);
        uint32_t wbase = (ks < 4) ? OFF_WS : OFF_WN;
        int kl = (ks & 3) * 16 + (lane & 15);
#pragma unroll
        for (int np = 0; np < 4; np++) {
            uint32_t b0, b1, b2, b3;
            ldsm_x4_t(b0, b1, b2, b3, sb + (wbase + kl * WS2 + np * 16 + acolq) * 2);
            mma16816(acc[np * 2],     a0, a1, a2, a3, b0, b1);
            mma16816(acc[np * 2 + 1], a0, a1, a2, a3, b2, b3);
        }
    }

    int r0 = base + wid * 16 + (lane >> 2);
    int r1 = r0 + 8;
    int cb = (lane & 3) * 2;
    float u0 = 0.f, t0 = 0.f, u1 = 0.f, t1 = 0.f;
#pragma unroll
    for (int nt = 0; nt < 8; nt++) {
        int c = nt * 8 + cb;
        float bb0 = sbias[c], bb1 = sbias[c + 1];
        float p0 = fmaxf(acc[nt][0] + bb0, 0.f);
        float p1 = fmaxf(acc[nt][1] + bb1, 0.f);
        float q0 = fmaxf(acc[nt][2] + bb0, 0.f);
        float q1 = fmaxf(acc[nt][3] + bb1, 0.f);
        if (out16) {
            if (r0 < NN)
                *(__half2*)(out16 + (size_t)r0 * DD + c) = __floats2half2_rn(p0, p1);
            if (r1 < NN)
                *(__half2*)(out16 + (size_t)r1 * DD + c) = __floats2half2_rn(q0, q1);
        }
        if (do_lin4) {
            u0 += p0 * sw4[c] + p1 * sw4[c + 1];
            t0 += p0 * sw4[64 + c] + p1 * sw4[64 + c + 1];
            u1 += q0 * sw4[c] + q1 * sw4[c + 1];
            t1 += q0 * sw4[64 + c] + q1 * sw4[64 + c + 1];
        }
    }
    if (do_lin4) {
        u0 += __shfl_xor_sync(0xffffffffu, u0, 1);
        u0 += __shfl_xor_sync(0xffffffffu, u0, 2);
        t0 += __shfl_xor_sync(0xffffffffu, t0, 1);
        t0 += __shfl_xor_sync(0xffffffffu, t0, 2);
        u1 += __shfl_xor_sync(0xffffffffu, u1, 1);
        u1 += __shfl_xor_sync(0xffffffffu, u1, 2);
        t1 += __shfl_xor_sync(0xffffffffu, t1, 1);
        t1 += __shfl_xor_sync(0xffffffffu, t1, 2);
        if ((lane & 3) == 0) {
            float bb = b4[0];
            if (r0 < NN) { g_u4[r0] = u0 + bb; g_t4[r0] = t0; }
            if (r1 < NN) { g_u4[r1] = u1 + bb; g_t4[r1] = t1; }
        }
    }
}

// ---------------- layer 4 output: sigmoid(u4 + deginv * sum t4[nbrs]) ----------------
__global__ void k_out4(float* __restrict__ out) {
    int node = blockIdx.x * 8 + (threadIdx.x >> 5);
    if (node >= NN) return;
    int lane = threadIdx.x & 31;
    int start = g_rowptr[node];
    int cnt   = g_cnt[node];
    float acc = 0.f;
    for (int j = lane; j < cnt; j += 32) acc += g_t4[g_col[start + j]];
#pragma unroll
    for (int o = 16; o; o >>= 1) acc += __shfl_down_sync(0xffffffffu, acc, o);
    if (lane == 0) {
        float z = g_u4[node] + g_deginv[node] * acc;
        out[node] = 1.0f / (1.0f + expf(-z));
    }
}

// ---------------- launch ----------------
extern "C" void kernel_launch(void* const* d_in, const int* in_sizes, int n_in,
                              void* d_out, int out_size) {
    const float* x   = (const float*)d_in[0];
    const void*  ei  = d_in[1];
    const float* Ws1 = (const float*)d_in[2];
    const float* Wn1 = (const float*)d_in[3];
    const float* b1  = (const float*)d_in[4];
    const float* Ws2 = (const float*)d_in[5];
    const float* Wn2 = (const float*)d_in[6];
    const float* b2  = (const float*)d_in[7];
    const float* Ws3 = (const float*)d_in[8];
    const float* Wn3 = (const float*)d_in[9];
    const float* b3  = (const float*)d_in[10];
    const float* Ws4 = (const float*)d_in[11];
    const float* Wn4 = (const float*)d_in[12];
    const float* b4  = (const float*)d_in[13];
    float* out = (float*)d_out;

    static __half *pHa = nullptr, *pHb = nullptr, *pAg = nullptr;
    if (!pHa) {
        void* p;
        cudaGetSymbolAddress(&p, g_h16a);   pHa = (__half*)p;
        cudaGetSymbolAddress(&p, g_h16b);   pHb = (__half*)p;
        cudaGetSymbolAddress(&p, g_agg16);  pAg = (__half*)p;
        cudaFuncSetAttribute(k_gemm_hmma, cudaFuncAttributeMaxDynamicSharedMemorySize,
                             SMEM_HM);
    }

    const int gridN4 = (NN + 3) / 4;
    const int gridN8 = (NN + 7) / 8;
    const int gridG  = (NN + 127) / 128;
    const int gridA  = (NN + 255) / 256;

    // CSR build (hist also converts x + weights; alloc replaces the scan)
    k_hist<<<GRID_E + 24, 256>>>(ei, x, pHa, Ws1, Wn1, Ws2, Wn2, Ws3, Wn3);
    k_alloc<<<gridA, 256>>>();
    k_fill<<<GRID_E, 256>>>(ei);

    // layer 1
    k_agg16<<<gridN4, 256>>>(pHa, pAg);
    k_gemm_hmma<<<gridG, 256, SMEM_HM>>>(pHa, pAg, 0, b1, pHb, Ws4, Wn4, b4, 0);
    // layer 2
    k_agg16<<<gridN4, 256>>>(pHb, pAg);
    k_gemm_hmma<<<gridG, 256, SMEM_HM>>>(pHb, pAg, 1, b2, pHa, Ws4, Wn4, b4, 0);
    // layer 3 (+ fused layer-4 linear; no layer-3 output store)
    k_agg16<<<gridN4, 256>>>(pHa, pAg);
    k_gemm_hmma<<<gridG, 256, SMEM_HM>>>(pHa, pAg, 2, b3, ((__half*)0), Ws4, Wn4, b4, 1);
    // layer 4 aggregation + sigmoid
    k_out4<<<gridN8, 256>>>(out);
}

// round 13
// speedup vs baseline: 1.2328x; 1.2328x over previous
#include <cuda_runtime.h>
#include <cuda_fp16.h>
#include <cstdint>

#define NN 100000
#define EE 1600000
#define DD 64
#define GRID_E 6250

// ---------------- scratch (device globals; no runtime allocation) ----------------
__device__ __align__(256) __half g_h16a [NN * DD];
__device__ __align__(256) __half g_h16b [NN * DD];
__device__ __align__(256) __half g_agg16[NN * DD];
__device__ __align__(256) __half g_w16[6 * 4096];   // Ws1,Wn1,Ws2,Wn2,Ws3,Wn3 fp16
__device__ int   g_cnt2[NN];     // atomic histogram (self-cleaning; starts zero)
__device__ int   g_cnt[NN];      // plain per-node degree
__device__ int   g_rowptr[NN];
__device__ int   g_cursor[NN];
__device__ int   g_col[EE];
__device__ float g_deginv[NN];
__device__ float g_t4[NN];
__device__ float g_u4[NN];
__device__ int   g_alloc;        // segment allocator (self-cleaning)
__device__ int   g_done;         // block done-counter (self-cleaning)

// ---------------- helpers ----------------
__device__ __forceinline__ uint32_t smem_u32(const void* p) {
    uint32_t a;
    asm("{ .reg .u64 t; cvta.to.shared.u64 t, %1; cvt.u32.u64 %0, t; }" : "=r"(a) : "l"(p));
    return a;
}
__device__ __forceinline__ long long edge_at(const void* ei, long long idx, int is64) {
    if (is64) return ((const long long*)ei)[idx];
    return (long long)((const int*)ei)[idx];
}
// per-warp dtype detection: high words of first 32 int64 pairs all zero => int64
__device__ __forceinline__ int detect64(const void* ei) {
    const unsigned* w = (const unsigned*)ei;
    unsigned lane = threadIdx.x & 31;
    bool z = (w[2 * lane + 1] == 0u);
    return __all_sync(0xffffffffu, z) ? 1 : 0;
}
__device__ __forceinline__ void ldsm_x4(uint32_t& r0, uint32_t& r1, uint32_t& r2,
                                        uint32_t& r3, uint32_t addr) {
    asm volatile("ldmatrix.sync.aligned.m8n8.x4.shared.b16 {%0,%1,%2,%3}, [%4];"
                 : "=r"(r0), "=r"(r1), "=r"(r2), "=r"(r3) : "r"(addr));
}
__device__ __forceinline__ void ldsm_x4_t(uint32_t& r0, uint32_t& r1, uint32_t& r2,
                                          uint32_t& r3, uint32_t addr) {
    asm volatile("ldmatrix.sync.aligned.m8n8.x4.trans.shared.b16 {%0,%1,%2,%3}, [%4];"
                 : "=r"(r0), "=r"(r1), "=r"(r2), "=r"(r3) : "r"(addr));
}
__device__ __forceinline__ void mma16816(float* d, uint32_t a0, uint32_t a1, uint32_t a2,
                                         uint32_t a3, uint32_t b0, uint32_t b1) {
    asm volatile(
        "mma.sync.aligned.m16n8k16.row.col.f32.f16.f16.f32 "
        "{%0,%1,%2,%3}, {%4,%5,%6,%7}, {%8,%9}, {%0,%1,%2,%3};"
        : "+f"(d[0]), "+f"(d[1]), "+f"(d[2]), "+f"(d[3])
        : "r"(a0), "r"(a1), "r"(a2), "r"(a3), "r"(b0), "r"(b1));
}
__device__ __forceinline__ int warp_iscan(int v, int lane) {
#pragma unroll
    for (int off = 1; off < 32; off <<= 1) {
        int t = __shfl_up_sync(0xffffffffu, v, off);
        if (lane >= off) v += t;
    }
    return v;
}

// ---------------- hist + x conv + weight conv (6250 edge blocks + 24 weight blocks) --
__global__ void k_hist(const void* __restrict__ ei, const float* __restrict__ x,
                       __half* __restrict__ o,
                       const float* __restrict__ Ws1, const float* __restrict__ Wn1,
                       const float* __restrict__ Ws2, const float* __restrict__ Wn2,
                       const float* __restrict__ Ws3, const float* __restrict__ Wn3) {
    if (blockIdx.x >= GRID_E) {
        int mb = blockIdx.x - GRID_E;       // 0..23
        int m = mb >> 2, seg = mb & 3;
        const float* srcs[6] = {Ws1, Wn1, Ws2, Wn2, Ws3, Wn3};
        const float* s = srcs[m];
        int base = seg * 1024;
        for (int i = threadIdx.x; i < 1024; i += 256)
            g_w16[m * 4096 + base + i] = __float2half_rn(s[base + i]);
        return;
    }
    int is64 = detect64(ei);
    int e = blockIdx.x * 256 + threadIdx.x;
    int d = (int)edge_at(ei, (long long)EE + e, is64);
    atomicAdd(&g_cnt2[d], 1);
    float4 v = ((const float4*)x)[e];
    ((__half2*)o)[2 * e]     = __floats2half2_rn(v.x, v.y);
    ((__half2*)o)[2 * e + 1] = __floats2half2_rn(v.z, v.w);
}

// ---------------- segment allocation (disjoint segments; one atomicAdd per warp) ----
__global__ void k_alloc() {
    int i = blockIdx.x * 256 + threadIdx.x;
    int lane = threadIdx.x & 31;
    int v = 0;
    if (i < NN) {
        v = g_cnt2[i];
        g_cnt2[i] = 0;                      // self-clean for next replay
        g_cnt[i] = v;
        g_deginv[i] = 1.0f / (float)(v > 0 ? v : 1);
    }
    int s = warp_iscan(v, lane);
    int wtot = __shfl_sync(0xffffffffu, s, 31);
    int base = 0;
    if (lane == 31) base = atomicAdd(&g_alloc, wtot);
    base = __shfl_sync(0xffffffffu, base, 31);
    if (i < NN) {
        int start = base + s - v;
        g_rowptr[i] = start;
        g_cursor[i] = start;
    }
    __syncthreads();
    if (threadIdx.x == 0) {
        int d = atomicAdd(&g_done, 1);
        if (d == (int)gridDim.x - 1) { g_alloc = 0; g_done = 0; }
    }
}

__global__ void k_fill(const void* __restrict__ ei) {
    int is64 = detect64(ei);
    int e = blockIdx.x * 256 + threadIdx.x;
    int dn = (int)edge_at(ei, (long long)EE + e, is64);
    int sn = (int)edge_at(ei, (long long)e, is64);
    int pos = atomicAdd(&g_cursor[dn], 1);
    g_col[pos] = sn;
}

// ---------------- aggregation: R10 structure + fp16 HADD2 accumulators ----------------
// warp per node; 4 groups of 8 lanes; 2 neighbor rows per group-iteration.
// Loop accumulates in half2 (8 HADD2/iter); fp32 conversion once per node.
__global__ __launch_bounds__(256) void k_agg16(const __half* __restrict__ h,
                                               __half* __restrict__ a) {
    int node = blockIdx.x * 8 + (threadIdx.x >> 5);
    if (node >= NN) return;
    int lane = threadIdx.x & 31;
    int g  = lane >> 3;
    int fl = lane & 7;
    int start = g_rowptr[node];
    int cnt   = g_cnt[node];
    const int* __restrict__ col = g_col + start;

    __half2 hacc[4];
    const __half2 hz = __float2half2_rn(0.f);
#pragma unroll
    for (int q = 0; q < 4; q++) hacc[q] = hz;

    for (int j = 2 * g; j < cnt; j += 8) {
        int c0 = col[j];
        uint4 v0 = *(const uint4*)(h + (size_t)c0 * DD + fl * 8);
        uint4 v1 = make_uint4(0u, 0u, 0u, 0u);
        if (j + 1 < cnt) {
            int c1 = col[j + 1];
            v1 = *(const uint4*)(h + (size_t)c1 * DD + fl * 8);
        }
        const __half2* a0 = (const __half2*)&v0;
        const __half2* a1 = (const __half2*)&v1;
#pragma unroll
        for (int q = 0; q < 4; q++)
            hacc[q] = __hadd2(hacc[q], __hadd2(a0[q], a1[q]));
    }

    // convert once per node, then fp32 cross-group reduction
    float acc[8];
#pragma unroll
    for (int q = 0; q < 4; q++) {
        float2 f = __half22float2(hacc[q]);
        acc[2 * q]     = f.x;
        acc[2 * q + 1] = f.y;
    }
#pragma unroll
    for (int q = 0; q < 8; q++) {
        acc[q] += __shfl_xor_sync(0xffffffffu, acc[q], 8);
        acc[q] += __shfl_xor_sync(0xffffffffu, acc[q], 16);
    }
    if (g == 0) {
        float di = g_deginv[node];
        __half2 o[4];
#pragma unroll
        for (int q = 0; q < 4; q++)
            o[q] = __floats2half2_rn(acc[2 * q] * di, acc[2 * q + 1] * di);
        *(uint4*)(a + (size_t)node * DD + fl * 8) = *(uint4*)o;
    }
}

// ---------------- HMMA fused GEMM + optional fused layer-4 linear ----------------
#define XS 136
#define WS2 72
#define OFF_WS (128 * XS)                      // halves
#define OFF_WN (OFF_WS + 64 * WS2)
#define OFF_BIAS_B ((OFF_WN + 64 * WS2) * 2)   // bytes
#define OFF_W4_B (OFF_BIAS_B + 64 * 4)
#define SMEM_HM (OFF_W4_B + 128 * 4)

__global__ __launch_bounds__(256) void k_gemm_hmma(
    const __half* __restrict__ h16, const __half* __restrict__ a16,
    int lidx, const float* __restrict__ bias, __half* __restrict__ out16,
    const float* __restrict__ ws4, const float* __restrict__ wn4,
    const float* __restrict__ b4, int do_lin4) {
    extern __shared__ char smem[];
    __half* sx = (__half*)smem;
    float* sbias = (float*)(smem + OFF_BIAS_B);
    float* sw4 = (float*)(smem + OFF_W4_B);
    uint32_t sb = smem_u32(smem);

    int tid = threadIdx.x, wid = tid >> 5, lane = tid & 31;
    int base = blockIdx.x * 128;

    const __half* w16 = g_w16 + lidx * 8192;   // Ws then Wn
    for (int idx = tid; idx < 1024; idx += 256) {
        int m = idx >> 9;
        int r = idx & 511;
        int k = r >> 3, ch = r & 7;
        uint4 v = ((const uint4*)(w16 + m * 4096))[r];
        *(uint4*)&sx[(m ? OFF_WN : OFF_WS) + k * WS2 + ch * 8] = v;
    }
    if (tid < 64) sbias[tid] = bias[tid];
    if (do_lin4 && tid < 64) { sw4[tid] = ws4[tid]; sw4[64 + tid] = wn4[tid]; }

    for (int idx = tid; idx < 128 * 16; idx += 256) {
        int r = idx >> 4, q = idx & 15;
        int node = base + r;
        uint4 v = make_uint4(0u, 0u, 0u, 0u);
        if (node < NN) {
            const __half* src = (q < 8) ? (h16 + (size_t)node * DD + q * 8)
                                        : (a16 + (size_t)node * DD + (q - 8) * 8);
            v = *(const uint4*)src;
        }
        *(uint4*)((char*)smem + (size_t)r * (XS * 2) + q * 16) = v;
    }
    __syncthreads();

    float acc[8][4];
#pragma unroll
    for (int nt = 0; nt < 8; nt++)
#pragma unroll
        for (int q = 0; q < 4; q++) acc[nt][q] = 0.f;

    int arow = wid * 16 + (lane & 15);
    int acolq = (lane >> 4) << 3;

#pragma unroll
    for (int ks = 0; ks < 8; ks++) {
        uint32_t a0, a1, a2, a3;
        ldsm_x4(a0, a1, a2, a3, sb + (arow * XS + ks * 16 + acolq) * 2);
        uint32_t wbase = (ks < 4) ? OFF_WS : OFF_WN;
        int kl = (ks & 3) * 16 + (lane & 15);
#pragma unroll
        for (int np = 0; np < 4; np++) {
            uint32_t b0, b1, b2, b3;
            ldsm_x4_t(b0, b1, b2, b3, sb + (wbase + kl * WS2 + np * 16 + acolq) * 2);
            mma16816(acc[np * 2],     a0, a1, a2, a3, b0, b1);
            mma16816(acc[np * 2 + 1], a0, a1, a2, a3, b2, b3);
        }
    }

    int r0 = base + wid * 16 + (lane >> 2);
    int r1 = r0 + 8;
    int cb = (lane & 3) * 2;
    float u0 = 0.f, t0 = 0.f, u1 = 0.f, t1 = 0.f;
#pragma unroll
    for (int nt = 0; nt < 8; nt++) {
        int c = nt * 8 + cb;
        float bb0 = sbias[c], bb1 = sbias[c + 1];
        float p0 = fmaxf(acc[nt][0] + bb0, 0.f);
        float p1 = fmaxf(acc[nt][1] + bb1, 0.f);
        float q0 = fmaxf(acc[nt][2] + bb0, 0.f);
        float q1 = fmaxf(acc[nt][3] + bb1, 0.f);
        if (out16) {
            if (r0 < NN)
                *(__half2*)(out16 + (size_t)r0 * DD + c) = __floats2half2_rn(p0, p1);
            if (r1 < NN)
                *(__half2*)(out16 + (size_t)r1 * DD + c) = __floats2half2_rn(q0, q1);
        }
        if (do_lin4) {
            u0 += p0 * sw4[c] + p1 * sw4[c + 1];
            t0 += p0 * sw4[64 + c] + p1 * sw4[64 + c + 1];
            u1 += q0 * sw4[c] + q1 * sw4[c + 1];
            t1 += q0 * sw4[64 + c] + q1 * sw4[64 + c + 1];
        }
    }
    if (do_lin4) {
        u0 += __shfl_xor_sync(0xffffffffu, u0, 1);
        u0 += __shfl_xor_sync(0xffffffffu, u0, 2);
        t0 += __shfl_xor_sync(0xffffffffu, t0, 1);
        t0 += __shfl_xor_sync(0xffffffffu, t0, 2);
        u1 += __shfl_xor_sync(0xffffffffu, u1, 1);
        u1 += __shfl_xor_sync(0xffffffffu, u1, 2);
        t1 += __shfl_xor_sync(0xffffffffu, t1, 1);
        t1 += __shfl_xor_sync(0xffffffffu, t1, 2);
        if ((lane & 3) == 0) {
            float bb = b4[0];
            if (r0 < NN) { g_u4[r0] = u0 + bb; g_t4[r0] = t0; }
            if (r1 < NN) { g_u4[r1] = u1 + bb; g_t4[r1] = t1; }
        }
    }
}

// ---------------- layer 4 output: sigmoid(u4 + deginv * sum t4[nbrs]) ----------------
__global__ void k_out4(float* __restrict__ out) {
    int node = blockIdx.x * 8 + (threadIdx.x >> 5);
    if (node >= NN) return;
    int lane = threadIdx.x & 31;
    int start = g_rowptr[node];
    int cnt   = g_cnt[node];
    float acc = 0.f;
    for (int j = lane; j < cnt; j += 32) acc += g_t4[g_col[start + j]];
#pragma unroll
    for (int o = 16; o; o >>= 1) acc += __shfl_down_sync(0xffffffffu, acc, o);
    if (lane == 0) {
        float z = g_u4[node] + g_deginv[node] * acc;
        out[node] = 1.0f / (1.0f + expf(-z));
    }
}

// ---------------- launch ----------------
extern "C" void kernel_launch(void* const* d_in, const int* in_sizes, int n_in,
                              void* d_out, int out_size) {
    const float* x   = (const float*)d_in[0];
    const void*  ei  = d_in[1];
    const float* Ws1 = (const float*)d_in[2];
    const float* Wn1 = (const float*)d_in[3];
    const float* b1  = (const float*)d_in[4];
    const float* Ws2 = (const float*)d_in[5];
    const float* Wn2 = (const float*)d_in[6];
    const float* b2  = (const float*)d_in[7];
    const float* Ws3 = (const float*)d_in[8];
    const float* Wn3 = (const float*)d_in[9];
    const float* b3  = (const float*)d_in[10];
    const float* Ws4 = (const float*)d_in[11];
    const float* Wn4 = (const float*)d_in[12];
    const float* b4  = (const float*)d_in[13];
    float* out = (float*)d_out;

    static __half *pHa = nullptr, *pHb = nullptr, *pAg = nullptr;
    if (!pHa) {
        void* p;
        cudaGetSymbolAddress(&p, g_h16a);   pHa = (__half*)p;
        cudaGetSymbolAddress(&p, g_h16b);   pHb = (__half*)p;
        cudaGetSymbolAddress(&p, g_agg16);  pAg = (__half*)p;
        cudaFuncSetAttribute(k_gemm_hmma, cudaFuncAttributeMaxDynamicSharedMemorySize,
                             SMEM_HM);
    }

    const int gridN8 = (NN + 7) / 8;
    const int gridG  = (NN + 127) / 128;
    const int gridA  = (NN + 255) / 256;

    // CSR build (hist also converts x + weights; alloc replaces the scan)
    k_hist<<<GRID_E + 24, 256>>>(ei, x, pHa, Ws1, Wn1, Ws2, Wn2, Ws3, Wn3);
    k_alloc<<<gridA, 256>>>();
    k_fill<<<GRID_E, 256>>>(ei);

    // layer 1
    k_agg16<<<gridN8, 256>>>(pHa, pAg);
    k_gemm_hmma<<<gridG, 256, SMEM_HM>>>(pHa, pAg, 0, b1, pHb, Ws4, Wn4, b4, 0);
    // layer 2
    k_agg16<<<gridN8, 256>>>(pHb, pAg);
    k_gemm_hmma<<<gridG, 256, SMEM_HM>>>(pHb, pAg, 1, b2, pHa, Ws4, Wn4, b4, 0);
    // layer 3 (+ fused layer-4 linear; no layer-3 output store)
    k_agg16<<<gridN8, 256>>>(pHa, pAg);
    k_gemm_hmma<<<gridG, 256, SMEM_HM>>>(pHa, pAg, 2, b3, ((__half*)0), Ws4, Wn4, b4, 1);
    // layer 4 aggregation + sigmoid
    k_out4<<<gridN8, 256>>>(out);
}

// round 14
// speedup vs baseline: 1.3939x; 1.1306x over previous
#include <cuda_runtime.h>
#include <cuda_fp16.h>
#include <cstdint>

#define NN 100000
#define EE 1600000
#define DD 64
#define GRID_E 6250

// ---------------- scratch (device globals; no runtime allocation) ----------------
__device__ __align__(256) __half g_h16a [NN * DD];
__device__ __align__(256) __half g_h16b [NN * DD];
__device__ __align__(256) __half g_agg16[NN * DD];
__device__ __align__(256) __half g_w16[6 * 4096];   // Ws1,Wn1,Ws2,Wn2,Ws3,Wn3 fp16
__device__ int   g_cnt2[NN];     // atomic histogram (self-cleaning; starts zero)
__device__ int   g_cnt[NN];      // plain per-node degree
__device__ int   g_rowptr[NN];
__device__ int   g_cursor[NN];
__device__ int   g_col[EE];
__device__ float g_deginv[NN];
__device__ float g_t4[NN];
__device__ float g_u4[NN];
__device__ int   g_alloc;        // segment allocator (self-cleaning)
__device__ int   g_done;         // block done-counter (self-cleaning)

// ---------------- helpers ----------------
__device__ __forceinline__ uint32_t smem_u32(const void* p) {
    uint32_t a;
    asm("{ .reg .u64 t; cvta.to.shared.u64 t, %1; cvt.u32.u64 %0, t; }" : "=r"(a) : "l"(p));
    return a;
}
__device__ __forceinline__ long long edge_at(const void* ei, long long idx, int is64) {
    if (is64) return ((const long long*)ei)[idx];
    return (long long)((const int*)ei)[idx];
}
// per-warp dtype detection: high words of first 32 int64 pairs all zero => int64
__device__ __forceinline__ int detect64(const void* ei) {
    const unsigned* w = (const unsigned*)ei;
    unsigned lane = threadIdx.x & 31;
    bool z = (w[2 * lane + 1] == 0u);
    return __all_sync(0xffffffffu, z) ? 1 : 0;
}
__device__ __forceinline__ void ldsm_x4(uint32_t& r0, uint32_t& r1, uint32_t& r2,
                                        uint32_t& r3, uint32_t addr) {
    asm volatile("ldmatrix.sync.aligned.m8n8.x4.shared.b16 {%0,%1,%2,%3}, [%4];"
                 : "=r"(r0), "=r"(r1), "=r"(r2), "=r"(r3) : "r"(addr));
}
__device__ __forceinline__ void ldsm_x4_t(uint32_t& r0, uint32_t& r1, uint32_t& r2,
                                          uint32_t& r3, uint32_t addr) {
    asm volatile("ldmatrix.sync.aligned.m8n8.x4.trans.shared.b16 {%0,%1,%2,%3}, [%4];"
                 : "=r"(r0), "=r"(r1), "=r"(r2), "=r"(r3) : "r"(addr));
}
__device__ __forceinline__ void mma16816(float* d, uint32_t a0, uint32_t a1, uint32_t a2,
                                         uint32_t a3, uint32_t b0, uint32_t b1) {
    asm volatile(
        "mma.sync.aligned.m16n8k16.row.col.f32.f16.f16.f32 "
        "{%0,%1,%2,%3}, {%4,%5,%6,%7}, {%8,%9}, {%0,%1,%2,%3};"
        : "+f"(d[0]), "+f"(d[1]), "+f"(d[2]), "+f"(d[3])
        : "r"(a0), "r"(a1), "r"(a2), "r"(a3), "r"(b0), "r"(b1));
}
__device__ __forceinline__ int warp_iscan(int v, int lane) {
#pragma unroll
    for (int off = 1; off < 32; off <<= 1) {
        int t = __shfl_up_sync(0xffffffffu, v, off);
        if (lane >= off) v += t;
    }
    return v;
}

// ---------------- hist + x conv + weight conv (6250 edge blocks + 24 weight blocks) --
__global__ void k_hist(const void* __restrict__ ei, const float* __restrict__ x,
                       __half* __restrict__ o,
                       const float* __restrict__ Ws1, const float* __restrict__ Wn1,
                       const float* __restrict__ Ws2, const float* __restrict__ Wn2,
                       const float* __restrict__ Ws3, const float* __restrict__ Wn3) {
    if (blockIdx.x >= GRID_E) {
        int mb = blockIdx.x - GRID_E;       // 0..23
        int m = mb >> 2, seg = mb & 3;
        const float* srcs[6] = {Ws1, Wn1, Ws2, Wn2, Ws3, Wn3};
        const float* s = srcs[m];
        int base = seg * 1024;
        for (int i = threadIdx.x; i < 1024; i += 256)
            g_w16[m * 4096 + base + i] = __float2half_rn(s[base + i]);
        return;
    }
    int is64 = detect64(ei);
    int e = blockIdx.x * 256 + threadIdx.x;
    int d = (int)edge_at(ei, (long long)EE + e, is64);
    atomicAdd(&g_cnt2[d], 1);
    float4 v = ((const float4*)x)[e];
    ((__half2*)o)[2 * e]     = __floats2half2_rn(v.x, v.y);
    ((__half2*)o)[2 * e + 1] = __floats2half2_rn(v.z, v.w);
}

// ---------------- segment allocation (disjoint segments; one atomicAdd per warp) ----
__global__ void k_alloc() {
    int i = blockIdx.x * 256 + threadIdx.x;
    int lane = threadIdx.x & 31;
    int v = 0;
    if (i < NN) {
        v = g_cnt2[i];
        g_cnt2[i] = 0;                      // self-clean for next replay
        g_cnt[i] = v;
        g_deginv[i] = 1.0f / (float)(v > 0 ? v : 1);
    }
    int s = warp_iscan(v, lane);
    int wtot = __shfl_sync(0xffffffffu, s, 31);
    int base = 0;
    if (lane == 31) base = atomicAdd(&g_alloc, wtot);
    base = __shfl_sync(0xffffffffu, base, 31);
    if (i < NN) {
        int start = base + s - v;
        g_rowptr[i] = start;
        g_cursor[i] = start;
    }
    __syncthreads();
    if (threadIdx.x == 0) {
        int d = atomicAdd(&g_done, 1);
        if (d == (int)gridDim.x - 1) { g_alloc = 0; g_done = 0; }
    }
}

__global__ void k_fill(const void* __restrict__ ei) {
    int is64 = detect64(ei);
    int e = blockIdx.x * 256 + threadIdx.x;
    int dn = (int)edge_at(ei, (long long)EE + e, is64);
    int sn = (int)edge_at(ei, (long long)e, is64);
    int pos = atomicAdd(&g_cursor[dn], 1);
    g_col[pos] = sn;
}

// ---------------- aggregation: one node per 8-lane group (NO cross-group reduction) --
// warp = 4 independent nodes; group g owns node, lanes fl cover the 128B row.
// Same per-edge arithmetic as R10/R13 (pairwise HADD2 + fp32 accumulate).
__global__ __launch_bounds__(256) void k_agg16(const __half* __restrict__ h,
                                               __half* __restrict__ a) {
    int lane = threadIdx.x & 31;
    int g  = lane >> 3;
    int fl = lane & 7;
    int node = blockIdx.x * 32 + (threadIdx.x >> 5) * 4 + g;
    bool valid = (node < NN);

    int start = 0, cnt = 0;
    if (valid) { start = g_rowptr[node]; cnt = g_cnt[node]; }
    const int* __restrict__ col = g_col + start;

    float acc[8];
#pragma unroll
    for (int q = 0; q < 8; q++) acc[q] = 0.f;

    for (int j = 0; j < cnt; j += 2) {
        int c0 = col[j];
        uint4 v0 = *(const uint4*)(h + (size_t)c0 * DD + fl * 8);
        uint4 v1 = make_uint4(0u, 0u, 0u, 0u);
        if (j + 1 < cnt) {
            int c1 = col[j + 1];
            v1 = *(const uint4*)(h + (size_t)c1 * DD + fl * 8);
        }
        const __half2* a0 = (const __half2*)&v0;
        const __half2* a1 = (const __half2*)&v1;
#pragma unroll
        for (int q = 0; q < 4; q++) {
            float2 f = __half22float2(__hadd2(a0[q], a1[q]));
            acc[2 * q]     += f.x;
            acc[2 * q + 1] += f.y;
        }
    }

    if (valid) {
        float di = g_deginv[node];
        __half2 o[4];
#pragma unroll
        for (int q = 0; q < 4; q++)
            o[q] = __floats2half2_rn(acc[2 * q] * di, acc[2 * q + 1] * di);
        *(uint4*)(a + (size_t)node * DD + fl * 8) = *(uint4*)o;
    }
}

// ---------------- HMMA fused GEMM + optional fused layer-4 linear ----------------
#define XS 136
#define WS2 72
#define OFF_WS (128 * XS)                      // halves
#define OFF_WN (OFF_WS + 64 * WS2)
#define OFF_BIAS_B ((OFF_WN + 64 * WS2) * 2)   // bytes
#define OFF_W4_B (OFF_BIAS_B + 64 * 4)
#define SMEM_HM (OFF_W4_B + 128 * 4)

__global__ __launch_bounds__(256) void k_gemm_hmma(
    const __half* __restrict__ h16, const __half* __restrict__ a16,
    int lidx, const float* __restrict__ bias, __half* __restrict__ out16,
    const float* __restrict__ ws4, const float* __restrict__ wn4,
    const float* __restrict__ b4, int do_lin4) {
    extern __shared__ char smem[];
    __half* sx = (__half*)smem;
    float* sbias = (float*)(smem + OFF_BIAS_B);
    float* sw4 = (float*)(smem + OFF_W4_B);
    uint32_t sb = smem_u32(smem);

    int tid = threadIdx.x, wid = tid >> 5, lane = tid & 31;
    int base = blockIdx.x * 128;

    const __half* w16 = g_w16 + lidx * 8192;   // Ws then Wn
    for (int idx = tid; idx < 1024; idx += 256) {
        int m = idx >> 9;
        int r = idx & 511;
        int k = r >> 3, ch = r & 7;
        uint4 v = ((const uint4*)(w16 + m * 4096))[r];
        *(uint4*)&sx[(m ? OFF_WN : OFF_WS) + k * WS2 + ch * 8] = v;
    }
    if (tid < 64) sbias[tid] = bias[tid];
    if (do_lin4 && tid < 64) { sw4[tid] = ws4[tid]; sw4[64 + tid] = wn4[tid]; }

    for (int idx = tid; idx < 128 * 16; idx += 256) {
        int r = idx >> 4, q = idx & 15;
        int node = base + r;
        uint4 v = make_uint4(0u, 0u, 0u, 0u);
        if (node < NN) {
            const __half* src = (q < 8) ? (h16 + (size_t)node * DD + q * 8)
                                        : (a16 + (size_t)node * DD + (q - 8) * 8);
            v = *(const uint4*)src;
        }
        *(uint4*)((char*)smem + (size_t)r * (XS * 2) + q * 16) = v;
    }
    __syncthreads();

    float acc[8][4];
#pragma unroll
    for (int nt = 0; nt < 8; nt++)
#pragma unroll
        for (int q = 0; q < 4; q++) acc[nt][q] = 0.f;

    int arow = wid * 16 + (lane & 15);
    int acolq = (lane >> 4) << 3;

#pragma unroll
    for (int ks = 0; ks < 8; ks++) {
        uint32_t a0, a1, a2, a3;
        ldsm_x4(a0, a1, a2, a3, sb + (arow * XS + ks * 16 + acolq) * 2);
        uint32_t wbase = (ks < 4) ? OFF_WS : OFF_WN;
        int kl = (ks & 3) * 16 + (lane & 15);
#pragma unroll
        for (int np = 0; np < 4; np++) {
            uint32_t b0, b1, b2, b3;
            ldsm_x4_t(b0, b1, b2, b3, sb + (wbase + kl * WS2 + np * 16 + acolq) * 2);
            mma16816(acc[np * 2],     a0, a1, a2, a3, b0, b1);
            mma16816(acc[np * 2 + 1], a0, a1, a2, a3, b2, b3);
        }
    }

    int r0 = base + wid * 16 + (lane >> 2);
    int r1 = r0 + 8;
    int cb = (lane & 3) * 2;
    float u0 = 0.f, t0 = 0.f, u1 = 0.f, t1 = 0.f;
#pragma unroll
    for (int nt = 0; nt < 8; nt++) {
        int c = nt * 8 + cb;
        float bb0 = sbias[c], bb1 = sbias[c + 1];
        float p0 = fmaxf(acc[nt][0] + bb0, 0.f);
        float p1 = fmaxf(acc[nt][1] + bb1, 0.f);
        float q0 = fmaxf(acc[nt][2] + bb0, 0.f);
        float q1 = fmaxf(acc[nt][3] + bb1, 0.f);
        if (out16) {
            if (r0 < NN)
                *(__half2*)(out16 + (size_t)r0 * DD + c) = __floats2half2_rn(p0, p1);
            if (r1 < NN)
                *(__half2*)(out16 + (size_t)r1 * DD + c) = __floats2half2_rn(q0, q1);
        }
        if (do_lin4) {
            u0 += p0 * sw4[c] + p1 * sw4[c + 1];
            t0 += p0 * sw4[64 + c] + p1 * sw4[64 + c + 1];
            u1 += q0 * sw4[c] + q1 * sw4[c + 1];
            t1 += q0 * sw4[64 + c] + q1 * sw4[64 + c + 1];
        }
    }
    if (do_lin4) {
        u0 += __shfl_xor_sync(0xffffffffu, u0, 1);
        u0 += __shfl_xor_sync(0xffffffffu, u0, 2);
        t0 += __shfl_xor_sync(0xffffffffu, t0, 1);
        t0 += __shfl_xor_sync(0xffffffffu, t0, 2);
        u1 += __shfl_xor_sync(0xffffffffu, u1, 1);
        u1 += __shfl_xor_sync(0xffffffffu, u1, 2);
        t1 += __shfl_xor_sync(0xffffffffu, t1, 1);
        t1 += __shfl_xor_sync(0xffffffffu, t1, 2);
        if ((lane & 3) == 0) {
            float bb = b4[0];
            if (r0 < NN) { g_u4[r0] = u0 + bb; g_t4[r0] = t0; }
            if (r1 < NN) { g_u4[r1] = u1 + bb; g_t4[r1] = t1; }
        }
    }
}

// ---------------- layer 4 output: sigmoid(u4 + deginv * sum t4[nbrs]) ----------------
__global__ void k_out4(float* __restrict__ out) {
    int node = blockIdx.x * 8 + (threadIdx.x >> 5);
    if (node >= NN) return;
    int lane = threadIdx.x & 31;
    int start = g_rowptr[node];
    int cnt   = g_cnt[node];
    float acc = 0.f;
    for (int j = lane; j < cnt; j += 32) acc += g_t4[g_col[start + j]];
#pragma unroll
    for (int o = 16; o; o >>= 1) acc += __shfl_down_sync(0xffffffffu, acc, o);
    if (lane == 0) {
        float z = g_u4[node] + g_deginv[node] * acc;
        out[node] = 1.0f / (1.0f + expf(-z));
    }
}

// ---------------- launch ----------------
extern "C" void kernel_launch(void* const* d_in, const int* in_sizes, int n_in,
                              void* d_out, int out_size) {
    const float* x   = (const float*)d_in[0];
    const void*  ei  = d_in[1];
    const float* Ws1 = (const float*)d_in[2];
    const float* Wn1 = (const float*)d_in[3];
    const float* b1  = (const float*)d_in[4];
    const float* Ws2 = (const float*)d_in[5];
    const float* Wn2 = (const float*)d_in[6];
    const float* b2  = (const float*)d_in[7];
    const float* Ws3 = (const float*)d_in[8];
    const float* Wn3 = (const float*)d_in[9];
    const float* b3  = (const float*)d_in[10];
    const float* Ws4 = (const float*)d_in[11];
    const float* Wn4 = (const float*)d_in[12];
    const float* b4  = (const float*)d_in[13];
    float* out = (float*)d_out;

    static __half *pHa = nullptr, *pHb = nullptr, *pAg = nullptr;
    if (!pHa) {
        void* p;
        cudaGetSymbolAddress(&p, g_h16a);   pHa = (__half*)p;
        cudaGetSymbolAddress(&p, g_h16b);   pHb = (__half*)p;
        cudaGetSymbolAddress(&p, g_agg16);  pAg = (__half*)p;
        cudaFuncSetAttribute(k_gemm_hmma, cudaFuncAttributeMaxDynamicSharedMemorySize,
                             SMEM_HM);
    }

    const int gridN32 = (NN + 31) / 32;
    const int gridN8  = (NN + 7) / 8;
    const int gridG   = (NN + 127) / 128;
    const int gridA   = (NN + 255) / 256;

    // CSR build (hist also converts x + weights; alloc replaces the scan)
    k_hist<<<GRID_E + 24, 256>>>(ei, x, pHa, Ws1, Wn1, Ws2, Wn2, Ws3, Wn3);
    k_alloc<<<gridA, 256>>>();
    k_fill<<<GRID_E, 256>>>(ei);

    // layer 1
    k_agg16<<<gridN32, 256>>>(pHa, pAg);
    k_gemm_hmma<<<gridG, 256, SMEM_HM>>>(pHa, pAg, 0, b1, pHb, Ws4, Wn4, b4, 0);
    // layer 2
    k_agg16<<<gridN32, 256>>>(pHb, pAg);
    k_gemm_hmma<<<gridG, 256, SMEM_HM>>>(pHb, pAg, 1, b2, pHa, Ws4, Wn4, b4, 0);
    // layer 3 (+ fused layer-4 linear; no layer-3 output store)
    k_agg16<<<gridN32, 256>>>(pHa, pAg);
    k_gemm_hmma<<<gridG, 256, SMEM_HM>>>(pHa, pAg, 2, b3, ((__half*)0), Ws4, Wn4, b4, 1);
    // layer 4 aggregation + sigmoid
    k_out4<<<gridN8, 256>>>(out);
}

// round 15
// speedup vs baseline: 1.3960x; 1.0016x over previous
#include <cuda_runtime.h>
#include <cuda_fp16.h>
#include <cstdint>

#define NN 100000
#define EE 1600000
#define DD 64
#define GRID_E 6250

// ---------------- scratch (device globals; no runtime allocation) ----------------
__device__ __align__(256) __half g_h16a [NN * DD];
__device__ __align__(256) __half g_h16b [NN * DD];
__device__ __align__(256) __half g_agg16[NN * DD];
__device__ __align__(256) __half g_w16[6 * 4096];   // Ws1,Wn1,Ws2,Wn2,Ws3,Wn3 fp16
__device__ int   g_cnt2[NN];     // atomic histogram (self-cleaning; starts zero)
__device__ int   g_cnt[NN];      // plain per-node degree
__device__ int   g_rowptr[NN];
__device__ int   g_cursor[NN];
__device__ int   g_col[EE];
__device__ float g_deginv[NN];
__device__ float g_t4[NN];
__device__ float g_u4[NN];
__device__ int   g_alloc;        // segment allocator (self-cleaning)
__device__ int   g_done;         // block done-counter (self-cleaning)

// ---------------- helpers ----------------
__device__ __forceinline__ uint32_t smem_u32(const void* p) {
    uint32_t a;
    asm("{ .reg .u64 t; cvta.to.shared.u64 t, %1; cvt.u32.u64 %0, t; }" : "=r"(a) : "l"(p));
    return a;
}
__device__ __forceinline__ long long edge_at(const void* ei, long long idx, int is64) {
    if (is64) return ((const long long*)ei)[idx];
    return (long long)((const int*)ei)[idx];
}
// per-warp dtype detection: high words of first 32 int64 pairs all zero => int64
__device__ __forceinline__ int detect64(const void* ei) {
    const unsigned* w = (const unsigned*)ei;
    unsigned lane = threadIdx.x & 31;
    bool z = (w[2 * lane + 1] == 0u);
    return __all_sync(0xffffffffu, z) ? 1 : 0;
}
__device__ __forceinline__ void ldsm_x4(uint32_t& r0, uint32_t& r1, uint32_t& r2,
                                        uint32_t& r3, uint32_t addr) {
    asm volatile("ldmatrix.sync.aligned.m8n8.x4.shared.b16 {%0,%1,%2,%3}, [%4];"
                 : "=r"(r0), "=r"(r1), "=r"(r2), "=r"(r3) : "r"(addr));
}
__device__ __forceinline__ void ldsm_x4_t(uint32_t& r0, uint32_t& r1, uint32_t& r2,
                                          uint32_t& r3, uint32_t addr) {
    asm volatile("ldmatrix.sync.aligned.m8n8.x4.trans.shared.b16 {%0,%1,%2,%3}, [%4];"
                 : "=r"(r0), "=r"(r1), "=r"(r2), "=r"(r3) : "r"(addr));
}
__device__ __forceinline__ void mma16816(float* d, uint32_t a0, uint32_t a1, uint32_t a2,
                                         uint32_t a3, uint32_t b0, uint32_t b1) {
    asm volatile(
        "mma.sync.aligned.m16n8k16.row.col.f32.f16.f16.f32 "
        "{%0,%1,%2,%3}, {%4,%5,%6,%7}, {%8,%9}, {%0,%1,%2,%3};"
        : "+f"(d[0]), "+f"(d[1]), "+f"(d[2]), "+f"(d[3])
        : "r"(a0), "r"(a1), "r"(a2), "r"(a3), "r"(b0), "r"(b1));
}
__device__ __forceinline__ int warp_iscan(int v, int lane) {
#pragma unroll
    for (int off = 1; off < 32; off <<= 1) {
        int t = __shfl_up_sync(0xffffffffu, v, off);
        if (lane >= off) v += t;
    }
    return v;
}

// ---------------- hist + x conv + weight conv (6250 edge blocks + 24 weight blocks) --
__global__ void k_hist(const void* __restrict__ ei, const float* __restrict__ x,
                       __half* __restrict__ o,
                       const float* __restrict__ Ws1, const float* __restrict__ Wn1,
                       const float* __restrict__ Ws2, const float* __restrict__ Wn2,
                       const float* __restrict__ Ws3, const float* __restrict__ Wn3) {
    if (blockIdx.x >= GRID_E) {
        int mb = blockIdx.x - GRID_E;       // 0..23
        int m = mb >> 2, seg = mb & 3;
        const float* srcs[6] = {Ws1, Wn1, Ws2, Wn2, Ws3, Wn3};
        const float* s = srcs[m];
        int base = seg * 1024;
        for (int i = threadIdx.x; i < 1024; i += 256)
            g_w16[m * 4096 + base + i] = __float2half_rn(s[base + i]);
        return;
    }
    int is64 = detect64(ei);
    int e = blockIdx.x * 256 + threadIdx.x;
    int d = (int)edge_at(ei, (long long)EE + e, is64);
    atomicAdd(&g_cnt2[d], 1);
    float4 v = ((const float4*)x)[e];
    ((__half2*)o)[2 * e]     = __floats2half2_rn(v.x, v.y);
    ((__half2*)o)[2 * e + 1] = __floats2half2_rn(v.z, v.w);
}

// ---------------- segment allocation (disjoint segments; one atomicAdd per warp) ----
__global__ void k_alloc() {
    int i = blockIdx.x * 256 + threadIdx.x;
    int lane = threadIdx.x & 31;
    int v = 0;
    if (i < NN) {
        v = g_cnt2[i];
        g_cnt2[i] = 0;                      // self-clean for next replay
        g_cnt[i] = v;
        g_deginv[i] = 1.0f / (float)(v > 0 ? v : 1);
    }
    int s = warp_iscan(v, lane);
    int wtot = __shfl_sync(0xffffffffu, s, 31);
    int base = 0;
    if (lane == 31) base = atomicAdd(&g_alloc, wtot);
    base = __shfl_sync(0xffffffffu, base, 31);
    if (i < NN) {
        int start = base + s - v;
        g_rowptr[i] = start;
        g_cursor[i] = start;
    }
    __syncthreads();
    if (threadIdx.x == 0) {
        int d = atomicAdd(&g_done, 1);
        if (d == (int)gridDim.x - 1) { g_alloc = 0; g_done = 0; }
    }
}

__global__ void k_fill(const void* __restrict__ ei) {
    int is64 = detect64(ei);
    int e = blockIdx.x * 256 + threadIdx.x;
    int dn = (int)edge_at(ei, (long long)EE + e, is64);
    int sn = (int)edge_at(ei, (long long)e, is64);
    int pos = atomicAdd(&g_cursor[dn], 1);
    g_col[pos] = sn;
}

// ---------------- aggregation: node-per-group + fp16 HADD2 accumulators -------------
// warp = 4 independent nodes (no cross-group reduction); loop accumulates in half2
// (8 HADD2 per 2 edges); one fp32 conversion + deginv scale per node.
__global__ __launch_bounds__(256) void k_agg16(const __half* __restrict__ h,
                                               __half* __restrict__ a) {
    int lane = threadIdx.x & 31;
    int g  = lane >> 3;
    int fl = lane & 7;
    int node = blockIdx.x * 32 + (threadIdx.x >> 5) * 4 + g;
    bool valid = (node < NN);

    int start = 0, cnt = 0;
    if (valid) { start = g_rowptr[node]; cnt = g_cnt[node]; }
    const int* __restrict__ col = g_col + start;

    __half2 hacc[4];
    const __half2 hz = __float2half2_rn(0.f);
#pragma unroll
    for (int q = 0; q < 4; q++) hacc[q] = hz;

    for (int j = 0; j < cnt; j += 2) {
        int c0 = col[j];
        uint4 v0 = *(const uint4*)(h + (size_t)c0 * DD + fl * 8);
        uint4 v1 = make_uint4(0u, 0u, 0u, 0u);
        if (j + 1 < cnt) {
            int c1 = col[j + 1];
            v1 = *(const uint4*)(h + (size_t)c1 * DD + fl * 8);
        }
        const __half2* a0 = (const __half2*)&v0;
        const __half2* a1 = (const __half2*)&v1;
#pragma unroll
        for (int q = 0; q < 4; q++)
            hacc[q] = __hadd2(hacc[q], __hadd2(a0[q], a1[q]));
    }

    if (valid) {
        float di = g_deginv[node];
        __half2 o[4];
#pragma unroll
        for (int q = 0; q < 4; q++) {
            float2 f = __half22float2(hacc[q]);
            o[q] = __floats2half2_rn(f.x * di, f.y * di);
        }
        *(uint4*)(a + (size_t)node * DD + fl * 8) = *(uint4*)o;
    }
}

// ---------------- HMMA fused GEMM + optional fused layer-4 linear ----------------
#define XS 136
#define WS2 72
#define OFF_WS (128 * XS)                      // halves
#define OFF_WN (OFF_WS + 64 * WS2)
#define OFF_BIAS_B ((OFF_WN + 64 * WS2) * 2)   // bytes
#define OFF_W4_B (OFF_BIAS_B + 64 * 4)
#define SMEM_HM (OFF_W4_B + 128 * 4)

__global__ __launch_bounds__(256) void k_gemm_hmma(
    const __half* __restrict__ h16, const __half* __restrict__ a16,
    int lidx, const float* __restrict__ bias, __half* __restrict__ out16,
    const float* __restrict__ ws4, const float* __restrict__ wn4,
    const float* __restrict__ b4, int do_lin4) {
    extern __shared__ char smem[];
    __half* sx = (__half*)smem;
    float* sbias = (float*)(smem + OFF_BIAS_B);
    float* sw4 = (float*)(smem + OFF_W4_B);
    uint32_t sb = smem_u32(smem);

    int tid = threadIdx.x, wid = tid >> 5, lane = tid & 31;
    int base = blockIdx.x * 128;

    const __half* w16 = g_w16 + lidx * 8192;   // Ws then Wn
    for (int idx = tid; idx < 1024; idx += 256) {
        int m = idx >> 9;
        int r = idx & 511;
        int k = r >> 3, ch = r & 7;
        uint4 v = ((const uint4*)(w16 + m * 4096))[r];
        *(uint4*)&sx[(m ? OFF_WN : OFF_WS) + k * WS2 + ch * 8] = v;
    }
    if (tid < 64) sbias[tid] = bias[tid];
    if (do_lin4 && tid < 64) { sw4[tid] = ws4[tid]; sw4[64 + tid] = wn4[tid]; }

    for (int idx = tid; idx < 128 * 16; idx += 256) {
        int r = idx >> 4, q = idx & 15;
        int node = base + r;
        uint4 v = make_uint4(0u, 0u, 0u, 0u);
        if (node < NN) {
            const __half* src = (q < 8) ? (h16 + (size_t)node * DD + q * 8)
                                        : (a16 + (size_t)node * DD + (q - 8) * 8);
            v = *(const uint4*)src;
        }
        *(uint4*)((char*)smem + (size_t)r * (XS * 2) + q * 16) = v;
    }
    __syncthreads();

    float acc[8][4];
#pragma unroll
    for (int nt = 0; nt < 8; nt++)
#pragma unroll
        for (int q = 0; q < 4; q++) acc[nt][q] = 0.f;

    int arow = wid * 16 + (lane & 15);
    int acolq = (lane >> 4) << 3;

#pragma unroll
    for (int ks = 0; ks < 8; ks++) {
        uint32_t a0, a1, a2, a3;
        ldsm_x4(a0, a1, a2, a3, sb + (arow * XS + ks * 16 + acolq) * 2);
        uint32_t wbase = (ks < 4) ? OFF_WS : OFF_WN;
        int kl = (ks & 3) * 16 + (lane & 15);
#pragma unroll
        for (int np = 0; np < 4; np++) {
            uint32_t b0, b1, b2, b3;
            ldsm_x4_t(b0, b1, b2, b3, sb + (wbase + kl * WS2 + np * 16 + acolq) * 2);
            mma16816(acc[np * 2],     a0, a1, a2, a3, b0, b1);
            mma16816(acc[np * 2 + 1], a0, a1, a2, a3, b2, b3);
        }
    }

    int r0 = base + wid * 16 + (lane >> 2);
    int r1 = r0 + 8;
    int cb = (lane & 3) * 2;
    float u0 = 0.f, t0 = 0.f, u1 = 0.f, t1 = 0.f;
#pragma unroll
    for (int nt = 0; nt < 8; nt++) {
        int c = nt * 8 + cb;
        float bb0 = sbias[c], bb1 = sbias[c + 1];
        float p0 = fmaxf(acc[nt][0] + bb0, 0.f);
        float p1 = fmaxf(acc[nt][1] + bb1, 0.f);
        float q0 = fmaxf(acc[nt][2] + bb0, 0.f);
        float q1 = fmaxf(acc[nt][3] + bb1, 0.f);
        if (out16) {
            if (r0 < NN)
                *(__half2*)(out16 + (size_t)r0 * DD + c) = __floats2half2_rn(p0, p1);
            if (r1 < NN)
                *(__half2*)(out16 + (size_t)r1 * DD + c) = __floats2half2_rn(q0, q1);
        }
        if (do_lin4) {
            u0 += p0 * sw4[c] + p1 * sw4[c + 1];
            t0 += p0 * sw4[64 + c] + p1 * sw4[64 + c + 1];
            u1 += q0 * sw4[c] + q1 * sw4[c + 1];
            t1 += q0 * sw4[64 + c] + q1 * sw4[64 + c + 1];
        }
    }
    if (do_lin4) {
        u0 += __shfl_xor_sync(0xffffffffu, u0, 1);
        u0 += __shfl_xor_sync(0xffffffffu, u0, 2);
        t0 += __shfl_xor_sync(0xffffffffu, t0, 1);
        t0 += __shfl_xor_sync(0xffffffffu, t0, 2);
        u1 += __shfl_xor_sync(0xffffffffu, u1, 1);
        u1 += __shfl_xor_sync(0xffffffffu, u1, 2);
        t1 += __shfl_xor_sync(0xffffffffu, t1, 1);
        t1 += __shfl_xor_sync(0xffffffffu, t1, 2);
        if ((lane & 3) == 0) {
            float bb = b4[0];
            if (r0 < NN) { g_u4[r0] = u0 + bb; g_t4[r0] = t0; }
            if (r1 < NN) { g_u4[r1] = u1 + bb; g_t4[r1] = t1; }
        }
    }
}

// ---------------- layer 4 output: sigmoid(u4 + deginv * sum t4[nbrs]) ----------------
__global__ void k_out4(float* __restrict__ out) {
    int node = blockIdx.x * 8 + (threadIdx.x >> 5);
    if (node >= NN) return;
    int lane = threadIdx.x & 31;
    int start = g_rowptr[node];
    int cnt   = g_cnt[node];
    float acc = 0.f;
    for (int j = lane; j < cnt; j += 32) acc += g_t4[g_col[start + j]];
#pragma unroll
    for (int o = 16; o; o >>= 1) acc += __shfl_down_sync(0xffffffffu, acc, o);
    if (lane == 0) {
        float z = g_u4[node] + g_deginv[node] * acc;
        out[node] = 1.0f / (1.0f + expf(-z));
    }
}

// ---------------- launch ----------------
extern "C" void kernel_launch(void* const* d_in, const int* in_sizes, int n_in,
                              void* d_out, int out_size) {
    const float* x   = (const float*)d_in[0];
    const void*  ei  = d_in[1];
    const float* Ws1 = (const float*)d_in[2];
    const float* Wn1 = (const float*)d_in[3];
    const float* b1  = (const float*)d_in[4];
    const float* Ws2 = (const float*)d_in[5];
    const float* Wn2 = (const float*)d_in[6];
    const float* b2  = (const float*)d_in[7];
    const float* Ws3 = (const float*)d_in[8];
    const float* Wn3 = (const float*)d_in[9];
    const float* b3  = (const float*)d_in[10];
    const float* Ws4 = (const float*)d_in[11];
    const float* Wn4 = (const float*)d_in[12];
    const float* b4  = (const float*)d_in[13];
    float* out = (float*)d_out;

    static __half *pHa = nullptr, *pHb = nullptr, *pAg = nullptr;
    if (!pHa) {
        void* p;
        cudaGetSymbolAddress(&p, g_h16a);   pHa = (__half*)p;
        cudaGetSymbolAddress(&p, g_h16b);   pHb = (__half*)p;
        cudaGetSymbolAddress(&p, g_agg16);  pAg = (__half*)p;
        cudaFuncSetAttribute(k_gemm_hmma, cudaFuncAttributeMaxDynamicSharedMemorySize,
                             SMEM_HM);
    }

    const int gridN32 = (NN + 31) / 32;
    const int gridN8  = (NN + 7) / 8;
    const int gridG   = (NN + 127) / 128;
    const int gridA   = (NN + 255) / 256;

    // CSR build (hist also converts x + weights; alloc replaces the scan)
    k_hist<<<GRID_E + 24, 256>>>(ei, x, pHa, Ws1, Wn1, Ws2, Wn2, Ws3, Wn3);
    k_alloc<<<gridA, 256>>>();
    k_fill<<<GRID_E, 256>>>(ei);

    // layer 1
    k_agg16<<<gridN32, 256>>>(pHa, pAg);
    k_gemm_hmma<<<gridG, 256, SMEM_HM>>>(pHa, pAg, 0, b1, pHb, Ws4, Wn4, b4, 0);
    // layer 2
    k_agg16<<<gridN32, 256>>>(pHb, pAg);
    k_gemm_hmma<<<gridG, 256, SMEM_HM>>>(pHb, pAg, 1, b2, pHa, Ws4, Wn4, b4, 0);
    // layer 3 (+ fused layer-4 linear; no layer-3 output store)
    k_agg16<<<gridN32, 256>>>(pHa, pAg);
    k_gemm_hmma<<<gridG, 256, SMEM_HM>>>(pHa, pAg, 2, b3, ((__half*)0), Ws4, Wn4, b4, 1);
    // layer 4 aggregation + sigmoid
    k_out4<<<gridN8, 256>>>(out);
}

// round 16
// speedup vs baseline: 1.4317x; 1.0256x over previous
#include <cuda_runtime.h>
#include <cuda_fp16.h>
#include <cstdint>

#define NN 100000
#define EE 1600000
#define DD 64
#define GRID_E 6250

// ---------------- scratch (device globals; no runtime allocation) ----------------
__device__ __align__(256) __half g_h16a [NN * DD];
__device__ __align__(256) __half g_h16b [NN * DD];
__device__ __align__(256) __half g_agg16[NN * DD];
__device__ __align__(256) __half g_w16[6 * 4096];   // Ws1,Wn1,Ws2,Wn2,Ws3,Wn3 fp16
__device__ int   g_cnt2[NN];     // atomic histogram (self-cleaning; starts zero)
__device__ int   g_cnt[NN];      // plain per-node degree
__device__ int   g_rowptr[NN];
__device__ int   g_cursor[NN];
__device__ int   g_col[EE];
__device__ float g_deginv[NN];
__device__ float g_t4[NN];
__device__ float g_u4[NN];
__device__ int   g_alloc;        // segment allocator (self-cleaning)
__device__ int   g_done;         // block done-counter (self-cleaning)

// ---------------- helpers ----------------
__device__ __forceinline__ uint32_t smem_u32(const void* p) {
    uint32_t a;
    asm("{ .reg .u64 t; cvta.to.shared.u64 t, %1; cvt.u32.u64 %0, t; }" : "=r"(a) : "l"(p));
    return a;
}
__device__ __forceinline__ long long edge_at(const void* ei, long long idx, int is64) {
    if (is64) return ((const long long*)ei)[idx];
    return (long long)((const int*)ei)[idx];
}
// per-warp dtype detection: high words of first 32 int64 pairs all zero => int64
__device__ __forceinline__ int detect64(const void* ei) {
    const unsigned* w = (const unsigned*)ei;
    unsigned lane = threadIdx.x & 31;
    bool z = (w[2 * lane + 1] == 0u);
    return __all_sync(0xffffffffu, z) ? 1 : 0;
}
__device__ __forceinline__ void ldsm_x4(uint32_t& r0, uint32_t& r1, uint32_t& r2,
                                        uint32_t& r3, uint32_t addr) {
    asm volatile("ldmatrix.sync.aligned.m8n8.x4.shared.b16 {%0,%1,%2,%3}, [%4];"
                 : "=r"(r0), "=r"(r1), "=r"(r2), "=r"(r3) : "r"(addr));
}
__device__ __forceinline__ void ldsm_x4_t(uint32_t& r0, uint32_t& r1, uint32_t& r2,
                                          uint32_t& r3, uint32_t addr) {
    asm volatile("ldmatrix.sync.aligned.m8n8.x4.trans.shared.b16 {%0,%1,%2,%3}, [%4];"
                 : "=r"(r0), "=r"(r1), "=r"(r2), "=r"(r3) : "r"(addr));
}
__device__ __forceinline__ void mma16816(float* d, uint32_t a0, uint32_t a1, uint32_t a2,
                                         uint32_t a3, uint32_t b0, uint32_t b1) {
    asm volatile(
        "mma.sync.aligned.m16n8k16.row.col.f32.f16.f16.f32 "
        "{%0,%1,%2,%3}, {%4,%5,%6,%7}, {%8,%9}, {%0,%1,%2,%3};"
        : "+f"(d[0]), "+f"(d[1]), "+f"(d[2]), "+f"(d[3])
        : "r"(a0), "r"(a1), "r"(a2), "r"(a3), "r"(b0), "r"(b1));
}
__device__ __forceinline__ int warp_iscan(int v, int lane) {
#pragma unroll
    for (int off = 1; off < 32; off <<= 1) {
        int t = __shfl_up_sync(0xffffffffu, v, off);
        if (lane >= off) v += t;
    }
    return v;
}

// ---------------- hist + x conv + weight conv (6250 edge blocks + 24 weight blocks) --
__global__ void k_hist(const void* __restrict__ ei, const float* __restrict__ x,
                       __half* __restrict__ o,
                       const float* __restrict__ Ws1, const float* __restrict__ Wn1,
                       const float* __restrict__ Ws2, const float* __restrict__ Wn2,
                       const float* __restrict__ Ws3, const float* __restrict__ Wn3) {
    if (blockIdx.x >= GRID_E) {
        int mb = blockIdx.x - GRID_E;       // 0..23
        int m = mb >> 2, seg = mb & 3;
        const float* srcs[6] = {Ws1, Wn1, Ws2, Wn2, Ws3, Wn3};
        const float* s = srcs[m];
        int base = seg * 1024;
        for (int i = threadIdx.x; i < 1024; i += 256)
            g_w16[m * 4096 + base + i] = __float2half_rn(s[base + i]);
        return;
    }
    int is64 = detect64(ei);
    int e = blockIdx.x * 256 + threadIdx.x;
    int d = (int)edge_at(ei, (long long)EE + e, is64);
    atomicAdd(&g_cnt2[d], 1);
    float4 v = ((const float4*)x)[e];
    ((__half2*)o)[2 * e]     = __floats2half2_rn(v.x, v.y);
    ((__half2*)o)[2 * e + 1] = __floats2half2_rn(v.z, v.w);
}

// ---------------- segment allocation (disjoint segments; one atomicAdd per warp) ----
__global__ void k_alloc() {
    int i = blockIdx.x * 256 + threadIdx.x;
    int lane = threadIdx.x & 31;
    int v = 0;
    if (i < NN) {
        v = g_cnt2[i];
        g_cnt2[i] = 0;                      // self-clean for next replay
        g_cnt[i] = v;
        g_deginv[i] = 1.0f / (float)(v > 0 ? v : 1);
    }
    int s = warp_iscan(v, lane);
    int wtot = __shfl_sync(0xffffffffu, s, 31);
    int base = 0;
    if (lane == 31) base = atomicAdd(&g_alloc, wtot);
    base = __shfl_sync(0xffffffffu, base, 31);
    if (i < NN) {
        int start = base + s - v;
        g_rowptr[i] = start;
        g_cursor[i] = start;
    }
    __syncthreads();
    if (threadIdx.x == 0) {
        int d = atomicAdd(&g_done, 1);
        if (d == (int)gridDim.x - 1) { g_alloc = 0; g_done = 0; }
    }
}

__global__ void k_fill(const void* __restrict__ ei) {
    int is64 = detect64(ei);
    int e = blockIdx.x * 256 + threadIdx.x;
    int dn = (int)edge_at(ei, (long long)EE + e, is64);
    int sn = (int)edge_at(ei, (long long)e, is64);
    int pos = atomicAdd(&g_cursor[dn], 1);
    g_col[pos] = sn;
}

// ---------------- aggregation: node-per-group, fp16 acc, 4 gathers in flight --------
// warp = 4 independent nodes; per iteration: 2 col loads + 4 independent row-gathers
// issue before any use (MLP ~6); fp16 HADD2 accumulate; fp32 scale once per node.
__global__ __launch_bounds__(256) void k_agg16(const __half* __restrict__ h,
                                               __half* __restrict__ a) {
    int lane = threadIdx.x & 31;
    int g  = lane >> 3;
    int fl = lane & 7;
    int node = blockIdx.x * 32 + (threadIdx.x >> 5) * 4 + g;
    bool valid = (node < NN);

    int start = 0, cnt = 0;
    if (valid) { start = g_rowptr[node]; cnt = g_cnt[node]; }
    const int* __restrict__ col = g_col + start;

    __half2 hacc[4];
    const __half2 hz = __float2half2_rn(0.f);
#pragma unroll
    for (int q = 0; q < 4; q++) hacc[q] = hz;

    const uint4 z4 = make_uint4(0u, 0u, 0u, 0u);
    for (int j = 0; j < cnt; j += 4) {
        int c0 = col[j];
        int c1 = (j + 1 < cnt) ? col[j + 1] : c0;
        int c2 = (j + 2 < cnt) ? col[j + 2] : c0;
        int c3 = (j + 3 < cnt) ? col[j + 3] : c0;
        uint4 v0 = *(const uint4*)(h + (size_t)c0 * DD + fl * 8);
        uint4 v1 = (j + 1 < cnt) ? *(const uint4*)(h + (size_t)c1 * DD + fl * 8) : z4;
        uint4 v2 = (j + 2 < cnt) ? *(const uint4*)(h + (size_t)c2 * DD + fl * 8) : z4;
        uint4 v3 = (j + 3 < cnt) ? *(const uint4*)(h + (size_t)c3 * DD + fl * 8) : z4;
        const __half2* a0 = (const __half2*)&v0;
        const __half2* a1 = (const __half2*)&v1;
        const __half2* a2 = (const __half2*)&v2;
        const __half2* a3 = (const __half2*)&v3;
#pragma unroll
        for (int q = 0; q < 4; q++)
            hacc[q] = __hadd2(hacc[q],
                              __hadd2(__hadd2(a0[q], a1[q]), __hadd2(a2[q], a3[q])));
    }

    if (valid) {
        float di = g_deginv[node];
        __half2 o[4];
#pragma unroll
        for (int q = 0; q < 4; q++) {
            float2 f = __half22float2(hacc[q]);
            o[q] = __floats2half2_rn(f.x * di, f.y * di);
        }
        *(uint4*)(a + (size_t)node * DD + fl * 8) = *(uint4*)o;
    }
}

// ---------------- HMMA fused GEMM + optional fused layer-4 linear ----------------
#define XS 136
#define WS2 72
#define OFF_WS (128 * XS)                      // halves
#define OFF_WN (OFF_WS + 64 * WS2)
#define OFF_BIAS_B ((OFF_WN + 64 * WS2) * 2)   // bytes
#define OFF_W4_B (OFF_BIAS_B + 64 * 4)
#define SMEM_HM (OFF_W4_B + 128 * 4)

__global__ __launch_bounds__(256) void k_gemm_hmma(
    const __half* __restrict__ h16, const __half* __restrict__ a16,
    int lidx, const float* __restrict__ bias, __half* __restrict__ out16,
    const float* __restrict__ ws4, const float* __restrict__ wn4,
    const float* __restrict__ b4, int do_lin4) {
    extern __shared__ char smem[];
    __half* sx = (__half*)smem;
    float* sbias = (float*)(smem + OFF_BIAS_B);
    float* sw4 = (float*)(smem + OFF_W4_B);
    uint32_t sb = smem_u32(smem);

    int tid = threadIdx.x, wid = tid >> 5, lane = tid & 31;
    int base = blockIdx.x * 128;

    const __half* w16 = g_w16 + lidx * 8192;   // Ws then Wn
    for (int idx = tid; idx < 1024; idx += 256) {
        int m = idx >> 9;
        int r = idx & 511;
        int k = r >> 3, ch = r & 7;
        uint4 v = ((const uint4*)(w16 + m * 4096))[r];
        *(uint4*)&sx[(m ? OFF_WN : OFF_WS) + k * WS2 + ch * 8] = v;
    }
    if (tid < 64) sbias[tid] = bias[tid];
    if (do_lin4 && tid < 64) { sw4[tid] = ws4[tid]; sw4[64 + tid] = wn4[tid]; }

    for (int idx = tid; idx < 128 * 16; idx += 256) {
        int r = idx >> 4, q = idx & 15;
        int node = base + r;
        uint4 v = make_uint4(0u, 0u, 0u, 0u);
        if (node < NN) {
            const __half* src = (q < 8) ? (h16 + (size_t)node * DD + q * 8)
                                        : (a16 + (size_t)node * DD + (q - 8) * 8);
            v = *(const uint4*)src;
        }
        *(uint4*)((char*)smem + (size_t)r * (XS * 2) + q * 16) = v;
    }
    __syncthreads();

    float acc[8][4];
#pragma unroll
    for (int nt = 0; nt < 8; nt++)
#pragma unroll
        for (int q = 0; q < 4; q++) acc[nt][q] = 0.f;

    int arow = wid * 16 + (lane & 15);
    int acolq = (lane >> 4) << 3;

#pragma unroll
    for (int ks = 0; ks < 8; ks++) {
        uint32_t a0, a1, a2, a3;
        ldsm_x4(a0, a1, a2, a3, sb + (arow * XS + ks * 16 + acolq) * 2);
        uint32_t wbase = (ks < 4) ? OFF_WS : OFF_WN;
        int kl = (ks & 3) * 16 + (lane & 15);
#pragma unroll
        for (int np = 0; np < 4; np++) {
            uint32_t b0, b1, b2, b3;
            ldsm_x4_t(b0, b1, b2, b3, sb + (wbase + kl * WS2 + np * 16 + acolq) * 2);
            mma16816(acc[np * 2],     a0, a1, a2, a3, b0, b1);
            mma16816(acc[np * 2 + 1], a0, a1, a2, a3, b2, b3);
        }
    }

    int r0 = base + wid * 16 + (lane >> 2);
    int r1 = r0 + 8;
    int cb = (lane & 3) * 2;
    float u0 = 0.f, t0 = 0.f, u1 = 0.f, t1 = 0.f;
#pragma unroll
    for (int nt = 0; nt < 8; nt++) {
        int c = nt * 8 + cb;
        float bb0 = sbias[c], bb1 = sbias[c + 1];
        float p0 = fmaxf(acc[nt][0] + bb0, 0.f);
        float p1 = fmaxf(acc[nt][1] + bb1, 0.f);
        float q0 = fmaxf(acc[nt][2] + bb0, 0.f);
        float q1 = fmaxf(acc[nt][3] + bb1, 0.f);
        if (out16) {
            if (r0 < NN)
                *(__half2*)(out16 + (size_t)r0 * DD + c) = __floats2half2_rn(p0, p1);
            if (r1 < NN)
                *(__half2*)(out16 + (size_t)r1 * DD + c) = __floats2half2_rn(q0, q1);
        }
        if (do_lin4) {
            u0 += p0 * sw4[c] + p1 * sw4[c + 1];
            t0 += p0 * sw4[64 + c] + p1 * sw4[64 + c + 1];
            u1 += q0 * sw4[c] + q1 * sw4[c + 1];
            t1 += q0 * sw4[64 + c] + q1 * sw4[64 + c + 1];
        }
    }
    if (do_lin4) {
        u0 += __shfl_xor_sync(0xffffffffu, u0, 1);
        u0 += __shfl_xor_sync(0xffffffffu, u0, 2);
        t0 += __shfl_xor_sync(0xffffffffu, t0, 1);
        t0 += __shfl_xor_sync(0xffffffffu, t0, 2);
        u1 += __shfl_xor_sync(0xffffffffu, u1, 1);
        u1 += __shfl_xor_sync(0xffffffffu, u1, 2);
        t1 += __shfl_xor_sync(0xffffffffu, t1, 1);
        t1 += __shfl_xor_sync(0xffffffffu, t1, 2);
        if ((lane & 3) == 0) {
            float bb = b4[0];
            if (r0 < NN) { g_u4[r0] = u0 + bb; g_t4[r0] = t0; }
            if (r1 < NN) { g_u4[r1] = u1 + bb; g_t4[r1] = t1; }
        }
    }
}

// ---------------- layer 4 output: sigmoid(u4 + deginv * sum t4[nbrs]) ----------------
__global__ void k_out4(float* __restrict__ out) {
    int node = blockIdx.x * 8 + (threadIdx.x >> 5);
    if (node >= NN) return;
    int lane = threadIdx.x & 31;
    int start = g_rowptr[node];
    int cnt   = g_cnt[node];
    float acc = 0.f;
    for (int j = lane; j < cnt; j += 32) acc += g_t4[g_col[start + j]];
#pragma unroll
    for (int o = 16; o; o >>= 1) acc += __shfl_down_sync(0xffffffffu, acc, o);
    if (lane == 0) {
        float z = g_u4[node] + g_deginv[node] * acc;
        out[node] = 1.0f / (1.0f + expf(-z));
    }
}

// ---------------- launch ----------------
extern "C" void kernel_launch(void* const* d_in, const int* in_sizes, int n_in,
                              void* d_out, int out_size) {
    const float* x   = (const float*)d_in[0];
    const void*  ei  = d_in[1];
    const float* Ws1 = (const float*)d_in[2];
    const float* Wn1 = (const float*)d_in[3];
    const float* b1  = (const float*)d_in[4];
    const float* Ws2 = (const float*)d_in[5];
    const float* Wn2 = (const float*)d_in[6];
    const float* b2  = (const float*)d_in[7];
    const float* Ws3 = (const float*)d_in[8];
    const float* Wn3 = (const float*)d_in[9];
    const float* b3  = (const float*)d_in[10];
    const float* Ws4 = (const float*)d_in[11];
    const float* Wn4 = (const float*)d_in[12];
    const float* b4  = (const float*)d_in[13];
    float* out = (float*)d_out;

    static __half *pHa = nullptr, *pHb = nullptr, *pAg = nullptr;
    if (!pHa) {
        void* p;
        cudaGetSymbolAddress(&p, g_h16a);   pHa = (__half*)p;
        cudaGetSymbolAddress(&p, g_h16b);   pHb = (__half*)p;
        cudaGetSymbolAddress(&p, g_agg16);  pAg = (__half*)p;
        cudaFuncSetAttribute(k_gemm_hmma, cudaFuncAttributeMaxDynamicSharedMemorySize,
                             SMEM_HM);
    }

    const int gridN32 = (NN + 31) / 32;
    const int gridN8  = (NN + 7) / 8;
    const int gridG   = (NN + 127) / 128;
    const int gridA   = (NN + 255) / 256;

    // CSR build (hist also converts x + weights; alloc replaces the scan)
    k_hist<<<GRID_E + 24, 256>>>(ei, x, pHa, Ws1, Wn1, Ws2, Wn2, Ws3, Wn3);
    k_alloc<<<gridA, 256>>>();
    k_fill<<<GRID_E, 256>>>(ei);

    // layer 1
    k_agg16<<<gridN32, 256>>>(pHa, pAg);
    k_gemm_hmma<<<gridG, 256, SMEM_HM>>>(pHa, pAg, 0, b1, pHb, Ws4, Wn4, b4, 0);
    // layer 2
    k_agg16<<<gridN32, 256>>>(pHb, pAg);
    k_gemm_hmma<<<gridG, 256, SMEM_HM>>>(pHb, pAg, 1, b2, pHa, Ws4, Wn4, b4, 0);
    // layer 3 (+ fused layer-4 linear; no layer-3 output store)
    k_agg16<<<gridN32, 256>>>(pHa, pAg);
    k_gemm_hmma<<<gridG, 256, SMEM_HM>>>(pHa, pAg, 2, b3, ((__half*)0), Ws4, Wn4, b4, 1);
    // layer 4 aggregation + sigmoid
    k_out4<<<gridN8, 256>>>(out);
}